// round 3
// baseline (speedup 1.0000x reference)
#include <cuda_runtime.h>
#include <cstdint>
#include <cstddef>

// ---------------- problem constants ----------------
#define BB 16
#define HWN 4096         // H*W
#define KC 16            // clusters
#define FF 576           // C*9
#define OO 64
#define RR 8
#define MLPD 32

// ---------------- device scratch (static, allowed) ----------------
__device__ float g_patches[BB * HWN * FF];     // 151 MB  [b][n][f]
__device__ float g_kernels[BB * KC * FF * OO]; // 37.7 MB [b][k][f][o]
__device__ int   g_offs[BB * 17];
__device__ int   g_perm[BB * HWN];
__device__ float g_lowrank[BB * KC * RR];
__device__ float g_biasv[BB * KC * OO];

// ---------------- helpers ----------------
__device__ __forceinline__ uint32_t smem_u32(const void* p) {
    return (uint32_t)__cvta_generic_to_shared(p);
}
#define CP16(dst, src) asm volatile("cp.async.cg.shared.global [%0], [%1], 16;" :: "r"(dst), "l"(src))
#define CP_COMMIT()    asm volatile("cp.async.commit_group;")
#define CP_WAIT(n)     asm volatile("cp.async.wait_group %0;" :: "n"(n))

__device__ __forceinline__ unsigned long long pack2(float v) {
    unsigned long long r;
    uint32_t u = __float_as_uint(v);
    asm("mov.b64 %0, {%1, %1};" : "=l"(r) : "r"(u));
    return r;
}
#define FMA2(d, a, b, c) asm("fma.rn.f32x2 %0, %1, %2, %3;" : "=l"(d) : "l"(a), "l"(b), "l"(c))

// ================= K1: unfold (build patches, coalesced) =================
// grid (64 y, 16 b), block 256, dyn smem = 64*195*4 = 49920 B
__global__ void unfold_kernel(const float* __restrict__ x) {
    extern __shared__ float sm[];   // [c][i][xx] stride c*195 + i*65 + xx
    const int y = blockIdx.x, b = blockIdx.y;

    for (int idx = threadIdx.x; idx < 64 * 3 * 64; idx += 256) {
        int c = idx / 192;
        int r = idx - c * 192;
        int i = r >> 6;
        int xx = r & 63;
        int yy = y + i - 1;
        float v = (yy >= 0 && yy < 64) ? x[(((size_t)(b * 64 + c)) * 64 + yy) * 64 + xx] : 0.f;
        sm[c * 195 + i * 65 + xx] = v;
    }
    __syncthreads();

    const int nbase = b * HWN + y * 64;
    for (int e = threadIdx.x; e < 64 * 144; e += 256) {
        int xq = e / 144;
        int f4 = e - xq * 144;
        int f = f4 << 2;
        float vq[4];
#pragma unroll
        for (int q = 0; q < 4; q++) {
            int ff = f + q;
            int c = ff / 9;
            int tap = ff - c * 9;
            int i = tap / 3;
            int j = tap - i * 3;
            int xx = xq + j - 1;
            vq[q] = (xx >= 0 && xx < 64) ? sm[c * 195 + i * 65 + xx] : 0.f;
        }
        float4 v = make_float4(vq[0], vq[1], vq[2], vq[3]);
        *reinterpret_cast<float4*>(&g_patches[(size_t)(nbase + xq) * FF + f]) = v;
    }
}

// ================= K2: counts + prefix + scatter (warp-aggregated atomics) =================
// grid 16 (batch), block 256
__global__ void count_scatter_kernel(const int* __restrict__ labels) {
    __shared__ int cnt[KC];
    __shared__ int offs[KC];
    const int b = blockIdx.x;
    const int lane = threadIdx.x & 31;
    if (threadIdx.x < KC) cnt[threadIdx.x] = 0;
    __syncthreads();

    for (int n = threadIdx.x; n < HWN; n += 256) {
        int k = labels[b * HWN + n];
        unsigned mask = __match_any_sync(0xffffffffu, k);
        if (lane == (__ffs(mask) - 1)) atomicAdd(&cnt[k], __popc(mask));
    }
    __syncthreads();
    if (threadIdx.x == 0) {
        int off = 0;
        for (int k = 0; k < KC; k++) {
            g_offs[b * 17 + k] = off;
            offs[k] = off;
            off += cnt[k];
        }
        g_offs[b * 17 + 16] = off;
    }
    __syncthreads();
    if (threadIdx.x < KC) cnt[threadIdx.x] = offs[threadIdx.x];  // cursors
    __syncthreads();

    for (int n = threadIdx.x; n < HWN; n += 256) {
        int k = labels[b * HWN + n];
        unsigned mask = __match_any_sync(0xffffffffu, k);
        int leader = __ffs(mask) - 1;
        int rank = __popc(mask & ((1u << lane) - 1u));
        int base = 0;
        if (lane == leader) base = atomicAdd(&cnt[k], __popc(mask));
        base = __shfl_sync(0xffffffffu, base, leader);
        g_perm[b * HWN + base + rank] = n;
    }
}

// ================= K3: centers (coalesced reduction over perm) + fused MLPs =================
// grid 256 (= b*16+k), block 192 (each thread owns cols t, t+192, t+384)
__global__ void centers_mlp_kernel(const float* __restrict__ lr_w1, const float* __restrict__ lr_b1,
                                   const float* __restrict__ lr_w2, const float* __restrict__ lr_b2,
                                   const float* __restrict__ lr_w3, const float* __restrict__ lr_b3,
                                   const float* __restrict__ bw1,   const float* __restrict__ bb1,
                                   const float* __restrict__ bw2,   const float* __restrict__ bb2) {
    __shared__ float cs[FF];
    __shared__ float h1[MLPD], h2[MLPD], t1v[MLPD];
    const int bk = blockIdx.x;
    const int b = bk >> 4;
    const int off = g_offs[bk + b];
    const int end = g_offs[bk + b + 1];
    const int nk = end - off;
    const int t = threadIdx.x;
    const int pb = b << 12;
    const int* __restrict__ pm = g_perm + pb + off;

    float s0 = 0, s1 = 0, s2 = 0;
    float u0 = 0, u1 = 0, u2 = 0;
    float v0 = 0, v1 = 0, v2 = 0;
    float w0 = 0, w1 = 0, w2 = 0;
    int r = 0;
    for (; r + 4 <= nk; r += 4) {
        const float* p0 = g_patches + (size_t)(pb + pm[r + 0]) * FF;
        const float* p1 = g_patches + (size_t)(pb + pm[r + 1]) * FF;
        const float* p2 = g_patches + (size_t)(pb + pm[r + 2]) * FF;
        const float* p3 = g_patches + (size_t)(pb + pm[r + 3]) * FF;
        s0 += p0[t]; s1 += p0[t + 192]; s2 += p0[t + 384];
        u0 += p1[t]; u1 += p1[t + 192]; u2 += p1[t + 384];
        v0 += p2[t]; v1 += p2[t + 192]; v2 += p2[t + 384];
        w0 += p3[t]; w1 += p3[t + 192]; w2 += p3[t + 384];
    }
    for (; r < nk; r++) {
        const float* p0 = g_patches + (size_t)(pb + pm[r]) * FF;
        s0 += p0[t]; s1 += p0[t + 192]; s2 += p0[t + 384];
    }
    const float inv = 1.0f / ((float)nk + 1e-6f);
    cs[t]       = (s0 + u0 + v0 + w0) * inv;
    cs[t + 192] = (s1 + u1 + v1 + w1) * inv;
    cs[t + 384] = (s2 + u2 + v2 + w2) * inv;
    __syncthreads();

    const int j = t;
    if (j < MLPD) {
        float s = lr_b1[j];
        float s2x = bb1[j];
        for (int f = 0; f < FF; f++) {
            float cv = cs[f];
            s   += cv * lr_w1[f * MLPD + j];
            s2x += cv * bw1[f * MLPD + j];
        }
        h1[j]  = fmaxf(s, 0.f);
        t1v[j] = fmaxf(s2x, 0.f);
    }
    __syncthreads();
    if (j < MLPD) {
        float s = lr_b2[j];
        for (int i = 0; i < MLPD; i++) s += h1[i] * lr_w2[i * MLPD + j];
        h2[j] = fmaxf(s, 0.f);
    }
    __syncthreads();
    if (j < RR) {
        float s = lr_b3[j];
        for (int i = 0; i < MLPD; i++) s += h2[i] * lr_w3[i * RR + j];
        g_lowrank[bk * RR + j] = s;
    }
    if (j < OO) {
        float s = bb2[j];
        for (int i = 0; i < MLPD; i++) s += t1v[i] * bw2[i * OO + j];
        g_biasv[bk * OO + j] = s;
    }
}

// ================= K4: fabricate per-cluster kernels =================
// kernels[bk][f][o] = sum_r lowrank[bk][r] * base[r][f][o]
// grid (36 f-chunks of 16 rows, 16 bk-groups of 16), block 256
__global__ void buildk_kernel(const float* __restrict__ base) {
    __shared__ float bs[RR][16 * 64];   // 32 KB
    __shared__ float lrs[16][RR];
    const int fb = blockIdx.x, gb = blockIdx.y;
    const int f0 = fb * 16;

    for (int idx = threadIdx.x; idx < RR * 1024; idx += 256) {
        int r = idx >> 10;
        int e = idx & 1023;
        bs[r][e] = base[((size_t)(r * FF + f0 + (e >> 6))) * OO + (e & 63)];
    }
    if (threadIdx.x < 16 * RR)
        lrs[threadIdx.x >> 3][threadIdx.x & 7] =
            g_lowrank[(gb * 16 + (threadIdx.x >> 3)) * RR + (threadIdx.x & 7)];
    __syncthreads();

    for (int bi = 0; bi < 16; bi++) {
        const int bk = gb * 16 + bi;
        float l[RR];
#pragma unroll
        for (int r = 0; r < RR; r++) l[r] = lrs[bi][r];
#pragma unroll
        for (int s = 0; s < 4; s++) {
            int e = threadIdx.x + (s << 8);
            float v = 0.f;
#pragma unroll
            for (int r = 0; r < RR; r++) v += l[r] * bs[r][e];
            g_kernels[(size_t)bk * (FF * OO) + f0 * OO + e] = v;
        }
    }
}

// ================= K5: grouped GEMM (fp32x2, 4Mx16N per thread) =================
// tile M=128, N=64, K chunks of 64. grid (256 bk, 16 m-tiles), block 128
// thread (tx=tid&3, ty=tid>>2): rows ty+{0,32,64,96}, cols tx*16+{0..15}
// dyn smem: A[2][128][68] (69632 B) + B[2][64][64] (32768 B) + rows[128] (512 B) = 102912 B
__global__ void __launch_bounds__(128, 2) gemm_kernel(float* __restrict__ out) {
    extern __shared__ char smraw[];
    float* Asm = (float*)smraw;                        // stride 68 per row
    float* Bsm = (float*)(smraw + 69632);
    int*  rows = (int*)(smraw + 69632 + 32768);

    const int bk = blockIdx.x;
    const int b = bk >> 4;
    const int off = g_offs[bk + b];        // b*17 + k
    const int end = g_offs[bk + b + 1];
    const int m0 = blockIdx.y << 7;
    if (off + m0 >= end) return;
    const int nk = end - off;
    const int tid = threadIdx.x;

    {
        int i = m0 + tid;
        rows[tid] = g_perm[(b << 12) + off + (i < nk ? i : 0)];
    }
    __syncthreads();

    const float* __restrict__ pb = g_patches + ((size_t)b << 12) * FF;
    const float* __restrict__ kb = g_kernels + (size_t)bk * (FF * OO);

    unsigned long long acc[32];
#pragma unroll
    for (int i = 0; i < 32; i++) acc[i] = 0ull;

    const int tx = tid & 3, ty = tid >> 2;

    // prologue: chunk 0
    {
#pragma unroll
        for (int s = 0; s < 16; s++) {
            int cid = tid + (s << 7);
            int row = cid >> 4, seg = (cid & 15) << 2;
            CP16(smem_u32(Asm + row * 68 + seg), pb + (size_t)rows[row] * FF + seg);
        }
#pragma unroll
        for (int s = 0; s < 8; s++) {
            int cid = (tid + (s << 7)) << 2;
            CP16(smem_u32(Bsm + cid), kb + cid);
        }
        CP_COMMIT();
    }

    for (int c = 0; c < 9; c++) {
        const int buf = c & 1;
        if (c < 8) {
            const int nb = buf ^ 1;
            const int kc = (c + 1) << 6;
#pragma unroll
            for (int s = 0; s < 16; s++) {
                int cid = tid + (s << 7);
                int row = cid >> 4, seg = (cid & 15) << 2;
                CP16(smem_u32(Asm + nb * 8704 + row * 68 + seg),
                     pb + (size_t)rows[row] * FF + kc + seg);
            }
#pragma unroll
            for (int s = 0; s < 8; s++) {
                int cid = (tid + (s << 7)) << 2;
                CP16(smem_u32(Bsm + nb * 4096 + cid), kb + (size_t)kc * 64 + cid);
            }
            CP_COMMIT();
            CP_WAIT(1);
        } else {
            CP_WAIT(0);
        }
        __syncthreads();

        const float* Ab = Asm + buf * 8704 + ty * 68;   // rows ty + 32j -> + j*2176
        const float* Bb = Bsm + buf * 4096 + (tx << 4);
#pragma unroll 8
        for (int kk = 0; kk < 64; kk++) {
            unsigned long long pa[4];
            pa[0] = pack2(Ab[kk]);
            pa[1] = pack2(Ab[kk + 2176]);
            pa[2] = pack2(Ab[kk + 4352]);
            pa[3] = pack2(Ab[kk + 6528]);
            float4 f0 = *reinterpret_cast<const float4*>(Bb + (kk << 6));
            float4 f1 = *reinterpret_cast<const float4*>(Bb + (kk << 6) + 4);
            float4 f2 = *reinterpret_cast<const float4*>(Bb + (kk << 6) + 8);
            float4 f3 = *reinterpret_cast<const float4*>(Bb + (kk << 6) + 12);
            ulonglong2 q0 = *reinterpret_cast<const ulonglong2*>(&f0);
            ulonglong2 q1 = *reinterpret_cast<const ulonglong2*>(&f1);
            ulonglong2 q2 = *reinterpret_cast<const ulonglong2*>(&f2);
            ulonglong2 q3 = *reinterpret_cast<const ulonglong2*>(&f3);
            unsigned long long bbv[8] = {q0.x, q0.y, q1.x, q1.y, q2.x, q2.y, q3.x, q3.y};
#pragma unroll
            for (int j = 0; j < 4; j++) {
#pragma unroll
                for (int p = 0; p < 8; p++) {
                    FMA2(acc[(j << 3) + p], pa[j], bbv[p], acc[(j << 3) + p]);
                }
            }
        }
        __syncthreads();
    }

    // epilogue: add cluster bias, scatter to out[b][o][n]
    float bias[16];
#pragma unroll
    for (int q = 0; q < 4; q++)
        *reinterpret_cast<float4*>(bias + (q << 2)) =
            *reinterpret_cast<const float4*>(g_biasv + (bk << 6) + (tx << 4) + (q << 2));

#pragma unroll
    for (int j = 0; j < 4; j++) {
        int i = m0 + ty + (j << 5);
        if (i < nk) {
            int n = rows[ty + (j << 5)];
#pragma unroll
            for (int p = 0; p < 8; p++) {
                uint32_t lo, hi;
                asm("mov.b64 {%0,%1}, %2;" : "=r"(lo), "=r"(hi) : "l"(acc[(j << 3) + p]));
                int o = (tx << 4) + (p << 1);
                out[(size_t)((b << 6) + o) * HWN + n]     = __uint_as_float(lo) + bias[(p << 1)];
                out[(size_t)((b << 6) + o + 1) * HWN + n] = __uint_as_float(hi) + bias[(p << 1) + 1];
            }
        }
    }
}

// ================= launch =================
extern "C" void kernel_launch(void* const* d_in, const int* in_sizes, int n_in,
                              void* d_out, int out_size) {
    const float* x      = (const float*)d_in[0];
    const int*   labels = (const int*)d_in[1];
    const float* lr_w1  = (const float*)d_in[2];
    const float* lr_b1  = (const float*)d_in[3];
    const float* lr_w2  = (const float*)d_in[4];
    const float* lr_b2  = (const float*)d_in[5];
    const float* lr_w3  = (const float*)d_in[6];
    const float* lr_b3  = (const float*)d_in[7];
    const float* base   = (const float*)d_in[8];
    const float* bw1    = (const float*)d_in[9];
    const float* bb1    = (const float*)d_in[10];
    const float* bw2    = (const float*)d_in[11];
    const float* bb2    = (const float*)d_in[12];
    float* out = (float*)d_out;

    cudaFuncSetAttribute(unfold_kernel, cudaFuncAttributeMaxDynamicSharedMemorySize, 50176);
    cudaFuncSetAttribute(gemm_kernel,   cudaFuncAttributeMaxDynamicSharedMemorySize, 102912);

    unfold_kernel<<<dim3(64, 16), 256, 49920>>>(x);
    count_scatter_kernel<<<16, 256>>>(labels);
    centers_mlp_kernel<<<256, 192>>>(lr_w1, lr_b1, lr_w2, lr_b2, lr_w3, lr_b3,
                                     bw1, bb1, bw2, bb2);
    buildk_kernel<<<dim3(36, 16), 256>>>(base);
    gemm_kernel<<<dim3(256, 16), 128, 102912>>>(out);
}

// round 5
// speedup vs baseline: 1.3541x; 1.3541x over previous
#include <cuda_runtime.h>
#include <cstdint>
#include <cstddef>

// ---------------- problem constants ----------------
#define BB 16
#define HWN 4096         // H*W
#define KC 16            // clusters
#define FF 576           // C*9
#define OO 64
#define RR 8
#define MLPD 32

// ---------------- device scratch ----------------
__device__ float g_patches[BB * HWN * FF];      // 151 MB  [b][n][f]
__device__ float g_kernT[BB * KC * OO * FF];    // 37.7 MB [b][k][o][f]  (transposed)
__device__ int   g_offs[BB * 17];
__device__ int   g_perm[BB * HWN];
__device__ float g_lowrank[BB * KC * RR];
__device__ float g_biasv[BB * KC * OO];

// ---------------- helpers ----------------
__device__ __forceinline__ uint32_t smem_u32(const void* p) {
    return (uint32_t)__cvta_generic_to_shared(p);
}
#define CP16(dst, src) asm volatile("cp.async.cg.shared.global [%0], [%1], 16;" :: "r"(dst), "l"(src))
#define CP_COMMIT()    asm volatile("cp.async.commit_group;")
#define CP_WAIT(n)     asm volatile("cp.async.wait_group %0;" :: "n"(n))

// split fp32 -> exact tf32 hi + tf32(lo)
__device__ __forceinline__ void split_tf32(float x, uint32_t& hi, uint32_t& lo) {
    uint32_t u = __float_as_uint(x);
    hi = u & 0xFFFFE000u;
    float l = x - __uint_as_float(hi);
    asm("cvt.rna.tf32.f32 %0, %1;" : "=r"(lo) : "f"(l));
}

#define MMA_TF32(d, a, b) \
    asm volatile("mma.sync.aligned.m16n8k8.row.col.f32.tf32.tf32.f32 " \
        "{%0,%1,%2,%3}, {%4,%5,%6,%7}, {%8,%9}, {%0,%1,%2,%3};" \
        : "+f"((d)[0]), "+f"((d)[1]), "+f"((d)[2]), "+f"((d)[3]) \
        : "r"((a)[0]), "r"((a)[1]), "r"((a)[2]), "r"((a)[3]), \
          "r"((b)[0]), "r"((b)[1]))

// ================= K1: unfold =================
__global__ void unfold_kernel(const float* __restrict__ x) {
    extern __shared__ float sm[];
    const int y = blockIdx.x, b = blockIdx.y;
    for (int idx = threadIdx.x; idx < 64 * 3 * 64; idx += 256) {
        int c = idx / 192;
        int r = idx - c * 192;
        int i = r >> 6;
        int xx = r & 63;
        int yy = y + i - 1;
        float v = (yy >= 0 && yy < 64) ? x[(((size_t)(b * 64 + c)) * 64 + yy) * 64 + xx] : 0.f;
        sm[c * 195 + i * 65 + xx] = v;
    }
    __syncthreads();
    const int nbase = b * HWN + y * 64;
    for (int e = threadIdx.x; e < 64 * 144; e += 256) {
        int xq = e / 144;
        int f4 = e - xq * 144;
        int f = f4 << 2;
        float vq[4];
#pragma unroll
        for (int q = 0; q < 4; q++) {
            int ff = f + q;
            int c = ff / 9;
            int tap = ff - c * 9;
            int i = tap / 3;
            int j = tap - i * 3;
            int xx = xq + j - 1;
            vq[q] = (xx >= 0 && xx < 64) ? sm[c * 195 + i * 65 + xx] : 0.f;
        }
        float4 v = make_float4(vq[0], vq[1], vq[2], vq[3]);
        *reinterpret_cast<float4*>(&g_patches[(size_t)(nbase + xq) * FF + f]) = v;
    }
}

// ================= K2: counts + prefix + scatter =================
__global__ void count_scatter_kernel(const int* __restrict__ labels) {
    __shared__ int cnt[KC];
    __shared__ int offs[KC];
    const int b = blockIdx.x;
    const int lane = threadIdx.x & 31;
    if (threadIdx.x < KC) cnt[threadIdx.x] = 0;
    __syncthreads();
    for (int n = threadIdx.x; n < HWN; n += 256) {
        int k = labels[b * HWN + n];
        unsigned mask = __match_any_sync(0xffffffffu, k);
        if (lane == (__ffs(mask) - 1)) atomicAdd(&cnt[k], __popc(mask));
    }
    __syncthreads();
    if (threadIdx.x == 0) {
        int off = 0;
        for (int k = 0; k < KC; k++) {
            g_offs[b * 17 + k] = off;
            offs[k] = off;
            off += cnt[k];
        }
        g_offs[b * 17 + 16] = off;
    }
    __syncthreads();
    if (threadIdx.x < KC) cnt[threadIdx.x] = offs[threadIdx.x];
    __syncthreads();
    for (int n = threadIdx.x; n < HWN; n += 256) {
        int k = labels[b * HWN + n];
        unsigned mask = __match_any_sync(0xffffffffu, k);
        int leader = __ffs(mask) - 1;
        int rank = __popc(mask & ((1u << lane) - 1u));
        int base = 0;
        if (lane == leader) base = atomicAdd(&cnt[k], __popc(mask));
        base = __shfl_sync(0xffffffffu, base, leader);
        g_perm[b * HWN + base + rank] = n;
    }
}

// ================= K3: centers + fused MLPs =================
__global__ void centers_mlp_kernel(const float* __restrict__ lr_w1, const float* __restrict__ lr_b1,
                                   const float* __restrict__ lr_w2, const float* __restrict__ lr_b2,
                                   const float* __restrict__ lr_w3, const float* __restrict__ lr_b3,
                                   const float* __restrict__ bw1,   const float* __restrict__ bb1,
                                   const float* __restrict__ bw2,   const float* __restrict__ bb2) {
    __shared__ float cs[FF];
    __shared__ float h1[MLPD], h2[MLPD], t1v[MLPD];
    const int bk = blockIdx.x;
    const int b = bk >> 4;
    const int off = g_offs[bk + b];
    const int end = g_offs[bk + b + 1];
    const int nk = end - off;
    const int t = threadIdx.x;
    const int pb = b << 12;
    const int* __restrict__ pm = g_perm + pb + off;

    float s0 = 0, s1 = 0, s2 = 0;
    float u0 = 0, u1 = 0, u2 = 0;
    float v0 = 0, v1 = 0, v2 = 0;
    float w0 = 0, w1 = 0, w2 = 0;
    int r = 0;
    for (; r + 4 <= nk; r += 4) {
        const float* p0 = g_patches + (size_t)(pb + pm[r + 0]) * FF;
        const float* p1 = g_patches + (size_t)(pb + pm[r + 1]) * FF;
        const float* p2 = g_patches + (size_t)(pb + pm[r + 2]) * FF;
        const float* p3 = g_patches + (size_t)(pb + pm[r + 3]) * FF;
        s0 += p0[t]; s1 += p0[t + 192]; s2 += p0[t + 384];
        u0 += p1[t]; u1 += p1[t + 192]; u2 += p1[t + 384];
        v0 += p2[t]; v1 += p2[t + 192]; v2 += p2[t + 384];
        w0 += p3[t]; w1 += p3[t + 192]; w2 += p3[t + 384];
    }
    for (; r < nk; r++) {
        const float* p0 = g_patches + (size_t)(pb + pm[r]) * FF;
        s0 += p0[t]; s1 += p0[t + 192]; s2 += p0[t + 384];
    }
    const float inv = 1.0f / ((float)nk + 1e-6f);
    cs[t]       = (s0 + u0 + v0 + w0) * inv;
    cs[t + 192] = (s1 + u1 + v1 + w1) * inv;
    cs[t + 384] = (s2 + u2 + v2 + w2) * inv;
    __syncthreads();

    const int j = t;
    if (j < MLPD) {
        float s = lr_b1[j];
        float s2x = bb1[j];
        for (int f = 0; f < FF; f++) {
            float cv = cs[f];
            s   += cv * lr_w1[f * MLPD + j];
            s2x += cv * bw1[f * MLPD + j];
        }
        h1[j]  = fmaxf(s, 0.f);
        t1v[j] = fmaxf(s2x, 0.f);
    }
    __syncthreads();
    if (j < MLPD) {
        float s = lr_b2[j];
        for (int i = 0; i < MLPD; i++) s += h1[i] * lr_w2[i * MLPD + j];
        h2[j] = fmaxf(s, 0.f);
    }
    __syncthreads();
    if (j < RR) {
        float s = lr_b3[j];
        for (int i = 0; i < MLPD; i++) s += h2[i] * lr_w3[i * RR + j];
        g_lowrank[bk * RR + j] = s;
    }
    if (j < OO) {
        float s = bb2[j];
        for (int i = 0; i < MLPD; i++) s += t1v[i] * bw2[i * OO + j];
        g_biasv[bk * OO + j] = s;
    }
}

// ================= K4: fabricate per-cluster kernels, TRANSPOSED [o][f] =================
__global__ void buildk_kernel(const float* __restrict__ base) {
    __shared__ float bs[RR][16 * 64];   // 32 KB
    __shared__ float lrs[16][RR];
    __shared__ float vsm[16 * 65];
    const int fb = blockIdx.x, gb = blockIdx.y;
    const int f0 = fb * 16;

    for (int idx = threadIdx.x; idx < RR * 1024; idx += 256) {
        int r = idx >> 10;
        int e = idx & 1023;
        bs[r][e] = base[((size_t)(r * FF + f0 + (e >> 6))) * OO + (e & 63)];
    }
    if (threadIdx.x < 16 * RR)
        lrs[threadIdx.x >> 3][threadIdx.x & 7] =
            g_lowrank[(gb * 16 + (threadIdx.x >> 3)) * RR + (threadIdx.x & 7)];
    __syncthreads();

    for (int bi = 0; bi < 16; bi++) {
        const int bk = gb * 16 + bi;
        float l[RR];
#pragma unroll
        for (int r = 0; r < RR; r++) l[r] = lrs[bi][r];
#pragma unroll
        for (int s = 0; s < 4; s++) {
            int e = threadIdx.x + (s << 8);
            int fl = e >> 6, o = e & 63;
            float v = 0.f;
#pragma unroll
            for (int r = 0; r < RR; r++) v += l[r] * bs[r][e];
            vsm[fl * 65 + o] = v;
        }
        __syncthreads();
#pragma unroll
        for (int s = 0; s < 4; s++) {
            int idx = threadIdx.x + (s << 8);
            int o = idx >> 4, fl = idx & 15;
            g_kernT[(size_t)bk * (OO * FF) + (size_t)o * FF + f0 + fl] = vsm[fl * 65 + o];
        }
        __syncthreads();
    }
}

// ================= K5: grouped GEMM via mma.sync tf32 (3x emulation) =================
// block tile M=128 N=64, K chunks of 64 (8 k8-steps). block 256 = 8 warps (4x2),
// warp tile 32x32. smem: A[2][128][68] 69632 B + B[2][64][68] 34816 B + rows 512 + bias 256
#define ASTR 68
#define GEMM_SMEM (69632 + 34816 + 512 + 256)

__global__ void __launch_bounds__(256, 2) gemm_kernel(float* __restrict__ out) {
    extern __shared__ char smraw[];
    float* Asm = (float*)smraw;                          // [2][128][68]
    float* Bsm = (float*)(smraw + 69632);                // [2][64][68]
    int*   rows  = (int*)(smraw + 69632 + 34816);
    float* sbias = (float*)(smraw + 69632 + 34816 + 512);

    const int bk = blockIdx.x;
    const int b = bk >> 4;
    const int off = g_offs[bk + b];
    const int end = g_offs[bk + b + 1];
    const int m0 = blockIdx.y << 7;
    if (off + m0 >= end) return;
    const int nk = end - off;
    const int tid = threadIdx.x;

    if (tid < 128) {
        int i = m0 + tid;
        rows[tid] = g_perm[(b << 12) + off + (i < nk ? i : 0)];
    }
    if (tid >= 128 && tid < 192) sbias[tid - 128] = g_biasv[(bk << 6) + tid - 128];
    __syncthreads();

    const float* __restrict__ pb = g_patches + ((size_t)b << 12) * FF;
    const float* __restrict__ kb = g_kernT + (size_t)bk * (OO * FF);

    const int lane = tid & 31, wid = tid >> 5;
    const int wm = (wid & 3) << 5;    // 0..96
    const int wn = (wid >> 2) << 5;   // 0,32
    const int qr = lane >> 2;         // 0..7
    const int qc = lane & 3;          // 0..3

    float d[2][4][4];
#pragma unroll
    for (int mf = 0; mf < 2; mf++)
#pragma unroll
        for (int nf = 0; nf < 4; nf++)
#pragma unroll
            for (int q = 0; q < 4; q++) d[mf][nf][q] = 0.f;

    // prologue: chunk 0
    {
#pragma unroll
        for (int s = 0; s < 8; s++) {
            int cid = tid + (s << 8);
            int row = cid >> 4, seg = (cid & 15) << 2;
            CP16(smem_u32(Asm + row * ASTR + seg), pb + (size_t)rows[row] * FF + seg);
        }
#pragma unroll
        for (int s = 0; s < 4; s++) {
            int cid = tid + (s << 8);
            int row = cid >> 4, seg = (cid & 15) << 2;
            CP16(smem_u32(Bsm + row * ASTR + seg), kb + (size_t)row * FF + seg);
        }
        CP_COMMIT();
    }

    for (int c = 0; c < 9; c++) {
        const int buf = c & 1;
        if (c < 8) {
            const int nb = buf ^ 1;
            const int kc = (c + 1) << 6;
#pragma unroll
            for (int s = 0; s < 8; s++) {
                int cid = tid + (s << 8);
                int row = cid >> 4, seg = (cid & 15) << 2;
                CP16(smem_u32(Asm + nb * 8704 + row * ASTR + seg),
                     pb + (size_t)rows[row] * FF + kc + seg);
            }
#pragma unroll
            for (int s = 0; s < 4; s++) {
                int cid = tid + (s << 8);
                int row = cid >> 4, seg = (cid & 15) << 2;
                CP16(smem_u32(Bsm + nb * 4352 + row * ASTR + seg),
                     kb + (size_t)row * FF + kc + seg);
            }
            CP_COMMIT();
            CP_WAIT(1);
        } else {
            CP_WAIT(0);
        }
        __syncthreads();

        const float* Ab = Asm + buf * 8704 + (wm + qr) * ASTR + qc;
        const float* Bb = Bsm + buf * 4352 + (wn + qr) * ASTR + qc;

#pragma unroll
        for (int s = 0; s < 8; s++) {
            const int k0 = s << 3;
            uint32_t ahi[2][4], alo[2][4], bhi[4][2], blo[4][2];
#pragma unroll
            for (int mf = 0; mf < 2; mf++) {
                const float* ap = Ab + mf * 1088 + k0;   // 1088 = 16*68
                split_tf32(ap[0],   ahi[mf][0], alo[mf][0]);
                split_tf32(ap[544], ahi[mf][1], alo[mf][1]);  // +8 rows
                split_tf32(ap[4],   ahi[mf][2], alo[mf][2]);
                split_tf32(ap[548], ahi[mf][3], alo[mf][3]);
            }
#pragma unroll
            for (int nf = 0; nf < 4; nf++) {
                const float* bp = Bb + nf * 544 + k0;    // 544 = 8*68
                split_tf32(bp[0], bhi[nf][0], blo[nf][0]);
                split_tf32(bp[4], bhi[nf][1], blo[nf][1]);
            }
#pragma unroll
            for (int mf = 0; mf < 2; mf++) {
#pragma unroll
                for (int nf = 0; nf < 4; nf++) {
                    MMA_TF32(d[mf][nf], ahi[mf], bhi[nf]);
                    MMA_TF32(d[mf][nf], ahi[mf], blo[nf]);
                    MMA_TF32(d[mf][nf], alo[mf], bhi[nf]);
                }
            }
        }
        __syncthreads();
    }

    // epilogue: scatter out[b][o][n] + bias
#pragma unroll
    for (int mf = 0; mf < 2; mf++) {
        const int r0 = wm + (mf << 4) + qr;
#pragma unroll
        for (int half = 0; half < 2; half++) {
            const int r = r0 + (half << 3);
            if (m0 + r < nk) {
                const int n = rows[r];
                float* ob = out + ((size_t)(b << 6)) * HWN + n;
#pragma unroll
                for (int nf = 0; nf < 4; nf++) {
                    const int o = wn + (nf << 3) + (qc << 1);
                    ob[(size_t)o * HWN]       = d[mf][nf][(half << 1)]     + sbias[o];
                    ob[(size_t)(o + 1) * HWN] = d[mf][nf][(half << 1) + 1] + sbias[o + 1];
                }
            }
        }
    }
}

// ================= launch =================
extern "C" void kernel_launch(void* const* d_in, const int* in_sizes, int n_in,
                              void* d_out, int out_size) {
    const float* x      = (const float*)d_in[0];
    const int*   labels = (const int*)d_in[1];
    const float* lr_w1  = (const float*)d_in[2];
    const float* lr_b1  = (const float*)d_in[3];
    const float* lr_w2  = (const float*)d_in[4];
    const float* lr_b2  = (const float*)d_in[5];
    const float* lr_w3  = (const float*)d_in[6];
    const float* lr_b3  = (const float*)d_in[7];
    const float* base   = (const float*)d_in[8];
    const float* bw1    = (const float*)d_in[9];
    const float* bb1    = (const float*)d_in[10];
    const float* bw2    = (const float*)d_in[11];
    const float* bb2    = (const float*)d_in[12];
    float* out = (float*)d_out;

    cudaFuncSetAttribute(unfold_kernel, cudaFuncAttributeMaxDynamicSharedMemorySize, 50176);
    cudaFuncSetAttribute(gemm_kernel,   cudaFuncAttributeMaxDynamicSharedMemorySize, GEMM_SMEM);

    unfold_kernel<<<dim3(64, 16), 256, 49920>>>(x);
    count_scatter_kernel<<<16, 256>>>(labels);
    centers_mlp_kernel<<<256, 192>>>(lr_w1, lr_b1, lr_w2, lr_b2, lr_w3, lr_b3,
                                     bw1, bb1, bw2, bb2);
    buildk_kernel<<<dim3(36, 16), 256>>>(base);
    gemm_kernel<<<dim3(256, 16), 256, GEMM_SMEM>>>(out);
}